// round 12
// baseline (speedup 1.0000x reference)
#include <cuda_runtime.h>

#define SEQ 4096
#define DM  1024
#define NH  16
#define D3  3072
#define LA  68     // attn smem row stride (floats)
#define LG  36     // gemm smem row stride (floats)

// tf32-rounded operands for the projection GEMM
__device__ float g_xr[SEQ * DM];    // x, rounded
__device__ float g_wt[D3 * DM];     // W^T [n][k], rounded
// fp32 scratch: kqv (K|Q|V), tf32-rounded, Q pre-scaled by 1/32
__device__ float g_kqv[SEQ * D3];
// V transposed per feature: g_vT[h*64+d][j]
__device__ float g_vT[DM * SEQ];

// ---------------------------------------------------------------------------
// helpers
// ---------------------------------------------------------------------------
static __device__ __forceinline__ unsigned s2u(const void* p) {
    return (unsigned)__cvta_generic_to_shared(p);
}
static __device__ __forceinline__ void ldsm4(unsigned* r, unsigned a) {
    asm volatile("ldmatrix.sync.aligned.m8n8.x4.shared.b16 {%0,%1,%2,%3}, [%4];"
                 : "=r"(r[0]), "=r"(r[1]), "=r"(r[2]), "=r"(r[3]) : "r"(a));
}
static __device__ __forceinline__ float tf32r(float x) {
    unsigned u; asm("cvt.rna.tf32.f32 %0, %1;" : "=r"(u) : "f"(x));
    return __uint_as_float(u);
}
static __device__ __forceinline__ void mma_tf32(float* c, const unsigned* a, const unsigned* b) {
    asm volatile("mma.sync.aligned.m16n8k8.row.col.f32.tf32.tf32.f32 "
                 "{%0,%1,%2,%3}, {%4,%5,%6,%7}, {%8,%9}, {%0,%1,%2,%3};"
                 : "+f"(c[0]), "+f"(c[1]), "+f"(c[2]), "+f"(c[3])
                 : "r"(a[0]), "r"(a[1]), "r"(a[2]), "r"(a[3]), "r"(b[0]), "r"(b[1]));
}
static __device__ __forceinline__ void ldA(unsigned* a, const float* base, int r0, int c0, int ld) {
    const int lane = threadIdx.x & 31;
    int row = r0 + (lane & 7) + ((lane >> 3) & 1) * 8;
    int col = c0 + (lane >> 4) * 4;
    ldsm4(a, s2u(base + row * ld + col));
}
static __device__ __forceinline__ void ldB(unsigned* b, const float* base, int n0, int c0, int ld) {
    const int lane = threadIdx.x & 31;
    int row = n0 + (lane & 7) + (lane >> 4) * 8;
    int col = c0 + ((lane >> 3) & 1) * 4;
    ldsm4(b, s2u(base + row * ld + col));
}
static __device__ __forceinline__ void cpa16(unsigned s, const void* g) {
    asm volatile("cp.async.cg.shared.global [%0], [%1], 16;" :: "r"(s), "l"(g) : "memory");
}
#define CP_COMMIT() asm volatile("cp.async.commit_group;" ::: "memory")
#define CP_WAIT(n)  asm volatile("cp.async.wait_group %0;" :: "n"(n) : "memory")

// ---------------------------------------------------------------------------
// Kernel 0a: round x -> g_xr (tf32, rna)
// ---------------------------------------------------------------------------
__global__ void round_x(const float* __restrict__ src, int n4) {
    int i = blockIdx.x * blockDim.x + threadIdx.x;
    if (i >= n4) return;
    float4 v = ((const float4*)src)[i];
    v.x = tf32r(v.x); v.y = tf32r(v.y); v.z = tf32r(v.z); v.w = tf32r(v.w);
    ((float4*)g_xr)[i] = v;
}

// ---------------------------------------------------------------------------
// Kernel 0b: transpose + round W[k][n] -> g_wt[n][k]
// ---------------------------------------------------------------------------
__global__ __launch_bounds__(256) void wtrans(const float* __restrict__ W) {
    __shared__ float t[32][33];
    const int x = threadIdx.x, y = threadIdx.y;   // 32 x 8
    const int n0 = blockIdx.x * 32, k0 = blockIdx.y * 32;
#pragma unroll
    for (int i = 0; i < 4; i++)
        t[y + i * 8][x] = W[(size_t)(k0 + y + i * 8) * D3 + n0 + x];
    __syncthreads();
#pragma unroll
    for (int i = 0; i < 4; i++) {
        int nn = y + i * 8;
        g_wt[(size_t)(n0 + nn) * DM + k0 + x] = tf32r(t[x][nn]);
    }
}

// ---------------------------------------------------------------------------
// Kernel 1: kqv = x @ w (tf32 mma.sync). CTA 128x128, BK=32, 8 warps (2m x 4n),
// double-buffered cp.async on pre-rounded operands. (unchanged from R9)
// ---------------------------------------------------------------------------
static __device__ __forceinline__ void gemm_stage_load(float* As, float* Bs,
                                                       int bm, int bn, int k0, int tid) {
#pragma unroll
    for (int p = 0; p < 4; p++) {
        int idx = tid + p * 256;
        int r = idx >> 3, c8 = idx & 7;
        cpa16(s2u(As + r * LG + c8 * 4), g_xr + (size_t)(bm + r) * DM + k0 + c8 * 4);
        cpa16(s2u(Bs + r * LG + c8 * 4), g_wt + (size_t)(bn + r) * DM + k0 + c8 * 4);
    }
}

__global__ __launch_bounds__(256) void gemm_kqv() {
    extern __shared__ __align__(16) float gsm[];
    const int tid = threadIdx.x, lane = tid & 31, wid = tid >> 5;
    const int bm = blockIdx.y * 128, bn = blockIdx.x * 128;
    const int wm = (wid >> 2) * 64, wn = (wid & 3) * 32;

    float c[4][4][4];
#pragma unroll
    for (int i = 0; i < 4; i++)
#pragma unroll
        for (int j = 0; j < 4; j++)
#pragma unroll
            for (int e = 0; e < 4; e++) c[i][j][e] = 0.f;

    gemm_stage_load(gsm, gsm + 4608, bm, bn, 0, tid);
    CP_COMMIT();

    for (int kc = 0; kc < 32; kc++) {
        if (kc < 31) {
            float* base = gsm + ((kc + 1) & 1) * 9216;
            gemm_stage_load(base, base + 4608, bm, bn, (kc + 1) * 32, tid);
        }
        CP_COMMIT();
        CP_WAIT(1);
        __syncthreads();

        const float* As = gsm + (kc & 1) * 9216;
        const float* Bs = As + 4608;
#pragma unroll
        for (int ks = 0; ks < 4; ks++) {
            unsigned af[4][4], bf[2][4];
#pragma unroll
            for (int mt = 0; mt < 4; mt++) ldA(af[mt], As, wm + mt * 16, ks * 8, LG);
#pragma unroll
            for (int np = 0; np < 2; np++) ldB(bf[np], Bs, wn + np * 16, ks * 8, LG);
#pragma unroll
            for (int mt = 0; mt < 4; mt++)
#pragma unroll
                for (int np = 0; np < 2; np++) {
                    mma_tf32(c[mt][np * 2],     af[mt], bf[np]);
                    mma_tf32(c[mt][np * 2 + 1], af[mt], bf[np] + 2);
                }
        }
        __syncthreads();
    }

    const float scl = (bn >= DM && bn < 2 * DM) ? 0.03125f : 1.0f;
#pragma unroll
    for (int mt = 0; mt < 4; mt++) {
        int r = bm + wm + mt * 16 + (lane >> 2);
#pragma unroll
        for (int nt = 0; nt < 4; nt++) {
            int col = bn + wn + nt * 8 + (lane & 3) * 2;
            *(float2*)&g_kqv[(size_t)r * D3 + col] =
                make_float2(tf32r(c[mt][nt][0] * scl), tf32r(c[mt][nt][1] * scl));
            *(float2*)&g_kqv[(size_t)(r + 8) * D3 + col] =
                make_float2(tf32r(c[mt][nt][2] * scl), tf32r(c[mt][nt][3] * scl));
        }
    }
}

// ---------------------------------------------------------------------------
// Kernel 1.5: transpose V chunk -> g_vT[c][j]
// ---------------------------------------------------------------------------
__global__ __launch_bounds__(256) void vtrans_kernel() {
    __shared__ float t[32][33];
    const int x = threadIdx.x, y = threadIdx.y;
    const int j0 = blockIdx.x * 32, c0 = blockIdx.y * 32;
#pragma unroll
    for (int k = 0; k < 4; k++)
        t[y + k * 8][x] = g_kqv[(size_t)(j0 + y + k * 8) * D3 + 2 * DM + c0 + x];
    __syncthreads();
#pragma unroll
    for (int k = 0; k < 4; k++)
        g_vT[(size_t)(c0 + y + k * 8) * SEQ + j0 + x] = t[x][y + k * 8];
}

// ---------------------------------------------------------------------------
// Kernel 2: flash attention — 8 warps x 16 rows (BM=128, BN=64).
// Same smem layout/pipeline as the 539us version; doubled warps/SM for
// latency hiding (16 warps/SM at 2 CTAs).
// smem: QS[128][LA] | PS[128][LA] | KS[64][LA] | VT[64][LA] = 104448 B
// ---------------------------------------------------------------------------
__global__ __launch_bounds__(256, 2) void attn_kernel(float* __restrict__ out) {
    extern __shared__ __align__(16) float sm[];
    float* QS = sm;
    float* PS = sm + 128 * LA;
    float* KS = sm + 256 * LA;
    float* VT = sm + 320 * LA;

    const int tid = threadIdx.x, lane = tid & 31, wid = tid >> 5;
    const int h = blockIdx.y;
    const int qt = (int)gridDim.x - 1 - (int)blockIdx.x;   // heavy tiles first
    const int q0 = qt * 128;
    const int wr = wid * 16;                               // 16 rows per warp
    const float slope = exp2f(-0.5f * (float)(h + 1));
    const int nt = 2 * qt + 2;

    // prologue: Q tile (128x64) + K(0) (64x64), one cp.async group
#pragma unroll
    for (int p = 0; p < 8; p++) {
        int ch = tid + p * 256;
        int r = ch >> 4, c4 = (ch & 15) * 4;
        cpa16(s2u(&QS[r * LA + c4]), g_kqv + (size_t)(q0 + r) * D3 + DM + h * 64 + c4);
    }
#pragma unroll
    for (int p = 0; p < 4; p++) {
        int ch = tid + p * 256;
        int r = ch >> 4, c4 = (ch & 15) * 4;
        cpa16(s2u(&KS[r * LA + c4]), g_kqv + (size_t)r * D3 + h * 64 + c4);
    }
    CP_COMMIT();

    float o[8][4];
#pragma unroll
    for (int ntl = 0; ntl < 8; ntl++)
#pragma unroll
        for (int e = 0; e < 4; e++) o[ntl][e] = 0.f;
    float m0 = -1e30f, m1 = -1e30f, l0 = 0.f, l1 = 0.f;

    for (int t = 0; t < nt; t++) {
        const int kv0 = t * 64;
        const bool active = (kv0 <= q0 + wr + 15);

        // issue V(t)  (overlaps S compute)
#pragma unroll
        for (int p = 0; p < 4; p++) {
            int ch = tid + p * 256;
            int d = ch >> 4, j4 = (ch & 15) * 4;
            cpa16(s2u(&VT[d * LA + j4]), g_vT + (size_t)(h * 64 + d) * SEQ + kv0 + j4);
        }
        CP_COMMIT();

        CP_WAIT(1);          // K(t) (+Q on t==0) ready; V(t) may still fly
        __syncthreads();

        float s[8][4];
        if (active) {
#pragma unroll
            for (int ntl = 0; ntl < 8; ntl++)
#pragma unroll
                for (int e = 0; e < 4; e++) s[ntl][e] = 0.f;
#pragma unroll
            for (int ks = 0; ks < 8; ks++) {
                unsigned qf[4];
                ldA(qf, QS, wr, ks * 8, LA);
#pragma unroll
                for (int np = 0; np < 4; np++) {
                    unsigned bf[4];
                    ldB(bf, KS, np * 16, ks * 8, LA);
                    mma_tf32(s[np * 2],     qf, bf);
                    mma_tf32(s[np * 2 + 1], qf, bf + 2);
                }
            }
        }
        __syncthreads();     // all warps done reading KS

        // prefetch K(t+1) (clamped; overlaps softmax + PV)
        {
            const int kvn = (t + 1 < nt ? t + 1 : t) * 64;
#pragma unroll
            for (int p = 0; p < 4; p++) {
                int ch = tid + p * 256;
                int r = ch >> 4, c4 = (ch & 15) * 4;
                cpa16(s2u(&KS[r * LA + c4]), g_kqv + (size_t)(kvn + r) * D3 + h * 64 + c4);
            }
            CP_COMMIT();
        }

        if (active) {
            const bool maskT = (t >= nt - 2);
            const int gi0 = q0 + wr + (lane >> 2);
            float ml0 = -1e30f, ml1 = -1e30f;
#pragma unroll
            for (int ntl = 0; ntl < 8; ntl++) {
#pragma unroll
                for (int e = 0; e < 2; e++) {
                    int gj = kv0 + ntl * 8 + (lane & 3) * 2 + e;
                    float v0 = fmaf(slope, (float)(gj - gi0), s[ntl][e]);
                    if (maskT && gj > gi0) v0 = -1e30f;
                    s[ntl][e] = v0; ml0 = fmaxf(ml0, v0);
                    float v1 = fmaf(slope, (float)(gj - (gi0 + 8)), s[ntl][2 + e]);
                    if (maskT && gj > gi0 + 8) v1 = -1e30f;
                    s[ntl][2 + e] = v1; ml1 = fmaxf(ml1, v1);
                }
            }
            ml0 = fmaxf(ml0, __shfl_xor_sync(0xffffffffu, ml0, 1));
            ml0 = fmaxf(ml0, __shfl_xor_sync(0xffffffffu, ml0, 2));
            ml1 = fmaxf(ml1, __shfl_xor_sync(0xffffffffu, ml1, 1));
            ml1 = fmaxf(ml1, __shfl_xor_sync(0xffffffffu, ml1, 2));
            float mn0 = fmaxf(m0, ml0), mn1 = fmaxf(m1, ml1);
            float a0 = __expf(m0 - mn0), a1 = __expf(m1 - mn1);
            m0 = mn0; m1 = mn1;
            float rs0 = 0.f, rs1 = 0.f;
#pragma unroll
            for (int ntl = 0; ntl < 8; ntl++) {
#pragma unroll
                for (int e = 0; e < 2; e++) {
                    float p0 = __expf(s[ntl][e] - mn0);     s[ntl][e] = p0;     rs0 += p0;
                    float p1 = __expf(s[ntl][2 + e] - mn1); s[ntl][2 + e] = p1; rs1 += p1;
                }
            }
            rs0 += __shfl_xor_sync(0xffffffffu, rs0, 1);
            rs0 += __shfl_xor_sync(0xffffffffu, rs0, 2);
            rs1 += __shfl_xor_sync(0xffffffffu, rs1, 1);
            rs1 += __shfl_xor_sync(0xffffffffu, rs1, 2);
            l0 = l0 * a0 + rs0;
            l1 = l1 * a1 + rs1;
#pragma unroll
            for (int ntl = 0; ntl < 8; ntl++) {
                o[ntl][0] *= a0; o[ntl][1] *= a0; o[ntl][2] *= a1; o[ntl][3] *= a1;
            }
            // stage P (own warp rows only)
            const int pr = wr + (lane >> 2);
            const int pc = (lane & 3) * 2;
#pragma unroll
            for (int ntl = 0; ntl < 8; ntl++) {
                *(float2*)&PS[pr * LA + ntl * 8 + pc] =
                    make_float2(tf32r(s[ntl][0]), tf32r(s[ntl][1]));
                *(float2*)&PS[(pr + 8) * LA + ntl * 8 + pc] =
                    make_float2(tf32r(s[ntl][2]), tf32r(s[ntl][3]));
            }
            __syncwarp();
        }

        CP_WAIT(1);          // V(t) ready; K(t+1) may still fly
        __syncthreads();

        if (active) {
#pragma unroll
            for (int jk = 0; jk < 8; jk++) {
                unsigned pf[4];
                ldA(pf, PS, wr, jk * 8, LA);
#pragma unroll
                for (int dp = 0; dp < 4; dp++) {
                    unsigned vf[4];
                    ldB(vf, VT, dp * 16, jk * 8, LA);
                    mma_tf32(o[dp * 2],     pf, vf);
                    mma_tf32(o[dp * 2 + 1], pf, vf + 2);
                }
            }
        }
        __syncthreads();     // all done with VT before next iteration's V issue
    }

    const float rl0 = 1.f / l0, rl1 = 1.f / l1;
    const int r = q0 + wr + (lane >> 2);
#pragma unroll
    for (int ntl = 0; ntl < 8; ntl++) {
        int col = h * 64 + ntl * 8 + (lane & 3) * 2;
        *(float2*)&out[(size_t)r * DM + col] =
            make_float2(o[ntl][0] * rl0, o[ntl][1] * rl0);
        *(float2*)&out[(size_t)(r + 8) * DM + col] =
            make_float2(o[ntl][2] * rl1, o[ntl][3] * rl1);
    }
}

// ---------------------------------------------------------------------------
// Launch
// ---------------------------------------------------------------------------
extern "C" void kernel_launch(void* const* d_in, const int* in_sizes, int n_in,
                              void* d_out, int out_size) {
    const float* x = (const float*)d_in[0];   // [1, 4096, 1024]
    const float* w = (const float*)d_in[1];   // [1024, 3072]
    float* out = (float*)d_out;

    const int gemm_smem = 2 * 2 * 128 * LG * (int)sizeof(float);   // 73728 B
    cudaFuncSetAttribute(gemm_kqv, cudaFuncAttributeMaxDynamicSharedMemorySize, gemm_smem);
    const int attn_smem = 384 * LA * (int)sizeof(float);           // 104448 B
    cudaFuncSetAttribute(attn_kernel, cudaFuncAttributeMaxDynamicSharedMemorySize, attn_smem);

    const int nx4 = SEQ * DM / 4;
    round_x<<<(nx4 + 255) / 256, 256>>>(x, nx4);
    wtrans<<<dim3(D3 / 32, DM / 32), dim3(32, 8)>>>(w);
    gemm_kqv<<<dim3(D3 / 128, SEQ / 128), 256, gemm_smem>>>();
    vtrans_kernel<<<dim3(SEQ / 32, DM / 32), dim3(32, 8)>>>();
    attn_kernel<<<dim3(SEQ / 128, NH), 256, attn_smem>>>(out);
}

// round 13
// speedup vs baseline: 1.7065x; 1.7065x over previous
#include <cuda_runtime.h>

#define SEQ 4096
#define DM  1024
#define NH  16
#define D3  3072
#define LA  68     // attn smem row stride (floats)
#define LG  36     // gemm smem row stride (floats)

// tf32-rounded operands for the projection GEMM
__device__ float g_xr[SEQ * DM];    // x, rounded
__device__ float g_wt[D3 * DM];     // W^T [n][k], rounded
// fp32 scratch: kqv (K|Q|V), tf32-rounded, Q pre-scaled by 1/32
__device__ float g_kqv[SEQ * D3];
// V transposed per feature: g_vT[h*64+d][j]
__device__ float g_vT[DM * SEQ];

// ---------------------------------------------------------------------------
// helpers
// ---------------------------------------------------------------------------
static __device__ __forceinline__ unsigned s2u(const void* p) {
    return (unsigned)__cvta_generic_to_shared(p);
}
static __device__ __forceinline__ void ldsm4(unsigned* r, unsigned a) {
    asm volatile("ldmatrix.sync.aligned.m8n8.x4.shared.b16 {%0,%1,%2,%3}, [%4];"
                 : "=r"(r[0]), "=r"(r[1]), "=r"(r[2]), "=r"(r[3]) : "r"(a));
}
static __device__ __forceinline__ float tf32r(float x) {
    unsigned u; asm("cvt.rna.tf32.f32 %0, %1;" : "=r"(u) : "f"(x));
    return __uint_as_float(u);
}
static __device__ __forceinline__ void mma_tf32(float* c, const unsigned* a, const unsigned* b) {
    asm volatile("mma.sync.aligned.m16n8k8.row.col.f32.tf32.tf32.f32 "
                 "{%0,%1,%2,%3}, {%4,%5,%6,%7}, {%8,%9}, {%0,%1,%2,%3};"
                 : "+f"(c[0]), "+f"(c[1]), "+f"(c[2]), "+f"(c[3])
                 : "r"(a[0]), "r"(a[1]), "r"(a[2]), "r"(a[3]), "r"(b[0]), "r"(b[1]));
}
static __device__ __forceinline__ void ldA(unsigned* a, const float* base, int r0, int c0, int ld) {
    const int lane = threadIdx.x & 31;
    int row = r0 + (lane & 7) + ((lane >> 3) & 1) * 8;
    int col = c0 + (lane >> 4) * 4;
    ldsm4(a, s2u(base + row * ld + col));
}
static __device__ __forceinline__ void ldB(unsigned* b, const float* base, int n0, int c0, int ld) {
    const int lane = threadIdx.x & 31;
    int row = n0 + (lane & 7) + (lane >> 4) * 8;
    int col = c0 + ((lane >> 3) & 1) * 4;
    ldsm4(b, s2u(base + row * ld + col));
}
static __device__ __forceinline__ void cpa16(unsigned s, const void* g) {
    asm volatile("cp.async.cg.shared.global [%0], [%1], 16;" :: "r"(s), "l"(g) : "memory");
}
#define CP_COMMIT() asm volatile("cp.async.commit_group;" ::: "memory")
#define CP_WAIT(n)  asm volatile("cp.async.wait_group %0;" :: "n"(n) : "memory")

// ---------------------------------------------------------------------------
// Kernel 0a: round x -> g_xr (tf32, rna)
// ---------------------------------------------------------------------------
__global__ void round_x(const float* __restrict__ src, int n4) {
    int i = blockIdx.x * blockDim.x + threadIdx.x;
    if (i >= n4) return;
    float4 v = ((const float4*)src)[i];
    v.x = tf32r(v.x); v.y = tf32r(v.y); v.z = tf32r(v.z); v.w = tf32r(v.w);
    ((float4*)g_xr)[i] = v;
}

// ---------------------------------------------------------------------------
// Kernel 0b: transpose + round W[k][n] -> g_wt[n][k]
// ---------------------------------------------------------------------------
__global__ __launch_bounds__(256) void wtrans(const float* __restrict__ W) {
    __shared__ float t[32][33];
    const int x = threadIdx.x, y = threadIdx.y;   // 32 x 8
    const int n0 = blockIdx.x * 32, k0 = blockIdx.y * 32;
#pragma unroll
    for (int i = 0; i < 4; i++)
        t[y + i * 8][x] = W[(size_t)(k0 + y + i * 8) * D3 + n0 + x];
    __syncthreads();
#pragma unroll
    for (int i = 0; i < 4; i++) {
        int nn = y + i * 8;
        g_wt[(size_t)(n0 + nn) * DM + k0 + x] = tf32r(t[x][nn]);
    }
}

// ---------------------------------------------------------------------------
// Kernel 1: kqv = x @ w (tf32 mma.sync). CTA 128x128, BK=32,
// 4 warps with 64x64 warp tiles (MMA/ldsm ratio 4.0), double-buffered cp.async.
// Epilogue: tf32-round, Q chunk pre-scaled by 1/32.
// ---------------------------------------------------------------------------
static __device__ __forceinline__ void gemm_stage_load(float* As, float* Bs,
                                                       int bm, int bn, int k0, int tid) {
#pragma unroll
    for (int p = 0; p < 8; p++) {
        int idx = tid + p * 128;
        int r = idx >> 3, c8 = idx & 7;
        cpa16(s2u(As + r * LG + c8 * 4), g_xr + (size_t)(bm + r) * DM + k0 + c8 * 4);
        cpa16(s2u(Bs + r * LG + c8 * 4), g_wt + (size_t)(bn + r) * DM + k0 + c8 * 4);
    }
}

__global__ __launch_bounds__(128) void gemm_kqv() {
    extern __shared__ __align__(16) float gsm[];
    const int tid = threadIdx.x, lane = tid & 31, wid = tid >> 5;
    const int bm = blockIdx.y * 128, bn = blockIdx.x * 128;
    const int wm = (wid >> 1) * 64, wn = (wid & 1) * 64;

    float c[4][8][4];
#pragma unroll
    for (int i = 0; i < 4; i++)
#pragma unroll
        for (int j = 0; j < 8; j++)
#pragma unroll
            for (int e = 0; e < 4; e++) c[i][j][e] = 0.f;

    gemm_stage_load(gsm, gsm + 4608, bm, bn, 0, tid);
    CP_COMMIT();

    for (int kc = 0; kc < 32; kc++) {
        if (kc < 31) {
            float* base = gsm + ((kc + 1) & 1) * 9216;
            gemm_stage_load(base, base + 4608, bm, bn, (kc + 1) * 32, tid);
        }
        CP_COMMIT();
        CP_WAIT(1);
        __syncthreads();

        const float* As = gsm + (kc & 1) * 9216;
        const float* Bs = As + 4608;
#pragma unroll
        for (int ks = 0; ks < 4; ks++) {
            unsigned af[4][4], bf[4][4];
#pragma unroll
            for (int mt = 0; mt < 4; mt++) ldA(af[mt], As, wm + mt * 16, ks * 8, LG);
#pragma unroll
            for (int np = 0; np < 4; np++) ldB(bf[np], Bs, wn + np * 16, ks * 8, LG);
#pragma unroll
            for (int mt = 0; mt < 4; mt++)
#pragma unroll
                for (int np = 0; np < 4; np++) {
                    mma_tf32(c[mt][np * 2],     af[mt], bf[np]);
                    mma_tf32(c[mt][np * 2 + 1], af[mt], bf[np] + 2);
                }
        }
        __syncthreads();
    }

    const float scl = (bn >= DM && bn < 2 * DM) ? 0.03125f : 1.0f;   // pre-scale Q
#pragma unroll
    for (int mt = 0; mt < 4; mt++) {
        int r = bm + wm + mt * 16 + (lane >> 2);
#pragma unroll
        for (int nt = 0; nt < 8; nt++) {
            int col = bn + wn + nt * 8 + (lane & 3) * 2;
            *(float2*)&g_kqv[(size_t)r * D3 + col] =
                make_float2(tf32r(c[mt][nt][0] * scl), tf32r(c[mt][nt][1] * scl));
            *(float2*)&g_kqv[(size_t)(r + 8) * D3 + col] =
                make_float2(tf32r(c[mt][nt][2] * scl), tf32r(c[mt][nt][3] * scl));
        }
    }
}

// ---------------------------------------------------------------------------
// Kernel 1.5: transpose V chunk -> g_vT[c][j]
// ---------------------------------------------------------------------------
__global__ __launch_bounds__(256) void vtrans_kernel() {
    __shared__ float t[32][33];
    const int x = threadIdx.x, y = threadIdx.y;
    const int j0 = blockIdx.x * 32, c0 = blockIdx.y * 32;
#pragma unroll
    for (int k = 0; k < 4; k++)
        t[y + k * 8][x] = g_kqv[(size_t)(j0 + y + k * 8) * D3 + 2 * DM + c0 + x];
    __syncthreads();
#pragma unroll
    for (int k = 0; k < 4; k++)
        g_vT[(size_t)(c0 + y + k * 8) * SEQ + j0 + x] = t[x][y + k * 8];
}

// ---------------------------------------------------------------------------
// Kernel 2: flash attention — EXACT 539us configuration (4 warps x 32 rows).
// Eager single-buffer cp.async: V(t) overlaps S(t); K(t+1) overlaps softmax+PV(t).
// smem: QS[128][LA] | PS[128][LA] | KS[64][LA] | VT[64][LA] = 104448 B (2 CTAs/SM)
// ---------------------------------------------------------------------------
__global__ __launch_bounds__(128, 2) void attn_kernel(float* __restrict__ out) {
    extern __shared__ __align__(16) float sm[];
    float* QS = sm;
    float* PS = sm + 128 * LA;
    float* KS = sm + 256 * LA;
    float* VT = sm + 320 * LA;

    const int tid = threadIdx.x, lane = tid & 31, wid = tid >> 5;
    const int h = blockIdx.y;
    const int qt = (int)gridDim.x - 1 - (int)blockIdx.x;
    const int q0 = qt * 128;
    const int wr = wid * 32;
    const float slope = exp2f(-0.5f * (float)(h + 1));
    const int nt = 2 * qt + 2;

#pragma unroll
    for (int p = 0; p < 16; p++) {
        int ch = tid + p * 128;
        int r = ch >> 4, c4 = (ch & 15) * 4;
        cpa16(s2u(&QS[r * LA + c4]), g_kqv + (size_t)(q0 + r) * D3 + DM + h * 64 + c4);
    }
#pragma unroll
    for (int p = 0; p < 8; p++) {
        int ch = tid + p * 128;
        int r = ch >> 4, c4 = (ch & 15) * 4;
        cpa16(s2u(&KS[r * LA + c4]), g_kqv + (size_t)r * D3 + h * 64 + c4);
    }
    CP_COMMIT();

    float o0[8][4], o1[8][4];
#pragma unroll
    for (int ntl = 0; ntl < 8; ntl++)
#pragma unroll
        for (int e = 0; e < 4; e++) { o0[ntl][e] = 0.f; o1[ntl][e] = 0.f; }
    float m[4] = {-1e30f, -1e30f, -1e30f, -1e30f};
    float l[4] = {0.f, 0.f, 0.f, 0.f};

    for (int t = 0; t < nt; t++) {
        const int kv0 = t * 64;
        const bool active = (kv0 <= q0 + wr + 31);

#pragma unroll
        for (int p = 0; p < 8; p++) {
            int ch = tid + p * 128;
            int d = ch >> 4, j4 = (ch & 15) * 4;
            cpa16(s2u(&VT[d * LA + j4]), g_vT + (size_t)(h * 64 + d) * SEQ + kv0 + j4);
        }
        CP_COMMIT();

        CP_WAIT(1);
        __syncthreads();

        float s0[8][4], s1[8][4];
        if (active) {
#pragma unroll
            for (int ntl = 0; ntl < 8; ntl++)
#pragma unroll
                for (int e = 0; e < 4; e++) { s0[ntl][e] = 0.f; s1[ntl][e] = 0.f; }
#pragma unroll
            for (int ks = 0; ks < 8; ks++) {
                unsigned qf0[4], qf1[4];
                ldA(qf0, QS, wr,      ks * 8, LA);
                ldA(qf1, QS, wr + 16, ks * 8, LA);
#pragma unroll
                for (int np = 0; np < 4; np++) {
                    unsigned bf[4];
                    ldB(bf, KS, np * 16, ks * 8, LA);
                    mma_tf32(s0[np * 2],     qf0, bf);
                    mma_tf32(s0[np * 2 + 1], qf0, bf + 2);
                    mma_tf32(s1[np * 2],     qf1, bf);
                    mma_tf32(s1[np * 2 + 1], qf1, bf + 2);
                }
            }
        }
        __syncthreads();

        {
            const int kvn = (t + 1 < nt ? t + 1 : t) * 64;
#pragma unroll
            for (int p = 0; p < 8; p++) {
                int ch = tid + p * 128;
                int r = ch >> 4, c4 = (ch & 15) * 4;
                cpa16(s2u(&KS[r * LA + c4]), g_kqv + (size_t)(kvn + r) * D3 + h * 64 + c4);
            }
            CP_COMMIT();
        }

        if (active) {
            const bool maskT = (t >= nt - 2);
#pragma unroll
            for (int mt = 0; mt < 2; mt++) {
                float (*s)[4] = mt ? s1 : s0;
                float (*o)[4] = mt ? o1 : o0;
                const int gi0 = q0 + wr + mt * 16 + (lane >> 2);
                float ml0 = -1e30f, ml1 = -1e30f;
#pragma unroll
                for (int ntl = 0; ntl < 8; ntl++) {
#pragma unroll
                    for (int e = 0; e < 2; e++) {
                        int gj = kv0 + ntl * 8 + (lane & 3) * 2 + e;
                        float v0 = fmaf(slope, (float)(gj - gi0), s[ntl][e]);
                        if (maskT && gj > gi0) v0 = -1e30f;
                        s[ntl][e] = v0; ml0 = fmaxf(ml0, v0);
                        float v1 = fmaf(slope, (float)(gj - (gi0 + 8)), s[ntl][2 + e]);
                        if (maskT && gj > gi0 + 8) v1 = -1e30f;
                        s[ntl][2 + e] = v1; ml1 = fmaxf(ml1, v1);
                    }
                }
                ml0 = fmaxf(ml0, __shfl_xor_sync(0xffffffffu, ml0, 1));
                ml0 = fmaxf(ml0, __shfl_xor_sync(0xffffffffu, ml0, 2));
                ml1 = fmaxf(ml1, __shfl_xor_sync(0xffffffffu, ml1, 1));
                ml1 = fmaxf(ml1, __shfl_xor_sync(0xffffffffu, ml1, 2));
                float mn0 = fmaxf(m[2 * mt], ml0), mn1 = fmaxf(m[2 * mt + 1], ml1);
                float a0 = __expf(m[2 * mt] - mn0), a1 = __expf(m[2 * mt + 1] - mn1);
                m[2 * mt] = mn0; m[2 * mt + 1] = mn1;
                float rs0 = 0.f, rs1 = 0.f;
#pragma unroll
                for (int ntl = 0; ntl < 8; ntl++) {
#pragma unroll
                    for (int e = 0; e < 2; e++) {
                        float p0 = __expf(s[ntl][e] - mn0);     s[ntl][e] = p0;     rs0 += p0;
                        float p1 = __expf(s[ntl][2 + e] - mn1); s[ntl][2 + e] = p1; rs1 += p1;
                    }
                }
                rs0 += __shfl_xor_sync(0xffffffffu, rs0, 1);
                rs0 += __shfl_xor_sync(0xffffffffu, rs0, 2);
                rs1 += __shfl_xor_sync(0xffffffffu, rs1, 1);
                rs1 += __shfl_xor_sync(0xffffffffu, rs1, 2);
                l[2 * mt]     = l[2 * mt] * a0 + rs0;
                l[2 * mt + 1] = l[2 * mt + 1] * a1 + rs1;
#pragma unroll
                for (int ntl = 0; ntl < 8; ntl++) {
                    o[ntl][0] *= a0; o[ntl][1] *= a0; o[ntl][2] *= a1; o[ntl][3] *= a1;
                }
                const int pr = wr + mt * 16 + (lane >> 2);
                const int pc = (lane & 3) * 2;
#pragma unroll
                for (int ntl = 0; ntl < 8; ntl++) {
                    *(float2*)&PS[pr * LA + ntl * 8 + pc] =
                        make_float2(tf32r(s[ntl][0]), tf32r(s[ntl][1]));
                    *(float2*)&PS[(pr + 8) * LA + ntl * 8 + pc] =
                        make_float2(tf32r(s[ntl][2]), tf32r(s[ntl][3]));
                }
            }
            __syncwarp();
        }

        CP_WAIT(1);
        __syncthreads();

        if (active) {
#pragma unroll
            for (int jk = 0; jk < 8; jk++) {
                unsigned pf0[4], pf1[4];
                ldA(pf0, PS, wr,      jk * 8, LA);
                ldA(pf1, PS, wr + 16, jk * 8, LA);
#pragma unroll
                for (int dp = 0; dp < 4; dp++) {
                    unsigned vf[4];
                    ldB(vf, VT, dp * 16, jk * 8, LA);
                    mma_tf32(o0[dp * 2],     pf0, vf);
                    mma_tf32(o0[dp * 2 + 1], pf0, vf + 2);
                    mma_tf32(o1[dp * 2],     pf1, vf);
                    mma_tf32(o1[dp * 2 + 1], pf1, vf + 2);
                }
            }
        }
        __syncthreads();
    }

    float rl[4] = {1.f / l[0], 1.f / l[1], 1.f / l[2], 1.f / l[3]};
#pragma unroll
    for (int mt = 0; mt < 2; mt++) {
        float (*o)[4] = mt ? o1 : o0;
        const int r = q0 + wr + mt * 16 + (lane >> 2);
#pragma unroll
        for (int ntl = 0; ntl < 8; ntl++) {
            int col = h * 64 + ntl * 8 + (lane & 3) * 2;
            *(float2*)&out[(size_t)r * DM + col] =
                make_float2(o[ntl][0] * rl[2 * mt], o[ntl][1] * rl[2 * mt]);
            *(float2*)&out[(size_t)(r + 8) * DM + col] =
                make_float2(o[ntl][2] * rl[2 * mt + 1], o[ntl][3] * rl[2 * mt + 1]);
        }
    }
}

// ---------------------------------------------------------------------------
// Launch
// ---------------------------------------------------------------------------
extern "C" void kernel_launch(void* const* d_in, const int* in_sizes, int n_in,
                              void* d_out, int out_size) {
    const float* x = (const float*)d_in[0];   // [1, 4096, 1024]
    const float* w = (const float*)d_in[1];   // [1024, 3072]
    float* out = (float*)d_out;

    const int gemm_smem = 2 * 2 * 128 * LG * (int)sizeof(float);   // 73728 B
    cudaFuncSetAttribute(gemm_kqv, cudaFuncAttributeMaxDynamicSharedMemorySize, gemm_smem);
    const int attn_smem = 384 * LA * (int)sizeof(float);           // 104448 B
    cudaFuncSetAttribute(attn_kernel, cudaFuncAttributeMaxDynamicSharedMemorySize, attn_smem);

    const int nx4 = SEQ * DM / 4;
    round_x<<<(nx4 + 255) / 256, 256>>>(x, nx4);
    wtrans<<<dim3(D3 / 32, DM / 32), dim3(32, 8)>>>(w);
    gemm_kqv<<<dim3(D3 / 128, SEQ / 128), 128, gemm_smem>>>();
    vtrans_kernel<<<dim3(SEQ / 32, DM / 32), dim3(32, 8)>>>();
    attn_kernel<<<dim3(SEQ / 128, NH), 128, attn_smem>>>(out);
}

// round 14
// speedup vs baseline: 1.7253x; 1.0111x over previous
#include <cuda_runtime.h>

#define SEQ 4096
#define DM  1024
#define NH  16
#define D3  3072
#define LA  68     // attn smem row stride (floats)
#define LG  36     // gemm smem row stride (floats)

// tf32-rounded operands for the projection GEMM
__device__ float g_xr[SEQ * DM];    // x, rounded
__device__ float g_wt[D3 * DM];     // W^T [n][k], rounded
// fp32 scratch: kqv (K|Q|V), tf32-rounded, Q pre-scaled by log2(e)/sqrt(D)
__device__ float g_kqv[SEQ * D3];
// V transposed per feature: g_vT[h*64+d][j]
__device__ float g_vT[DM * SEQ];

// ---------------------------------------------------------------------------
// helpers
// ---------------------------------------------------------------------------
static __device__ __forceinline__ unsigned s2u(const void* p) {
    return (unsigned)__cvta_generic_to_shared(p);
}
static __device__ __forceinline__ void ldsm4(unsigned* r, unsigned a) {
    asm volatile("ldmatrix.sync.aligned.m8n8.x4.shared.b16 {%0,%1,%2,%3}, [%4];"
                 : "=r"(r[0]), "=r"(r[1]), "=r"(r[2]), "=r"(r[3]) : "r"(a));
}
static __device__ __forceinline__ float tf32r(float x) {
    unsigned u; asm("cvt.rna.tf32.f32 %0, %1;" : "=r"(u) : "f"(x));
    return __uint_as_float(u);
}
static __device__ __forceinline__ void mma_tf32(float* c, const unsigned* a, const unsigned* b) {
    asm volatile("mma.sync.aligned.m16n8k8.row.col.f32.tf32.tf32.f32 "
                 "{%0,%1,%2,%3}, {%4,%5,%6,%7}, {%8,%9}, {%0,%1,%2,%3};"
                 : "+f"(c[0]), "+f"(c[1]), "+f"(c[2]), "+f"(c[3])
                 : "r"(a[0]), "r"(a[1]), "r"(a[2]), "r"(a[3]), "r"(b[0]), "r"(b[1]));
}
static __device__ __forceinline__ void ldA(unsigned* a, const float* base, int r0, int c0, int ld) {
    const int lane = threadIdx.x & 31;
    int row = r0 + (lane & 7) + ((lane >> 3) & 1) * 8;
    int col = c0 + (lane >> 4) * 4;
    ldsm4(a, s2u(base + row * ld + col));
}
static __device__ __forceinline__ void ldB(unsigned* b, const float* base, int n0, int c0, int ld) {
    const int lane = threadIdx.x & 31;
    int row = n0 + (lane & 7) + (lane >> 4) * 8;
    int col = c0 + ((lane >> 3) & 1) * 4;
    ldsm4(b, s2u(base + row * ld + col));
}
static __device__ __forceinline__ void cpa16(unsigned s, const void* g) {
    asm volatile("cp.async.cg.shared.global [%0], [%1], 16;" :: "r"(s), "l"(g) : "memory");
}
#define CP_COMMIT() asm volatile("cp.async.commit_group;" ::: "memory")
#define CP_WAIT(n)  asm volatile("cp.async.wait_group %0;" :: "n"(n) : "memory")

// ---------------------------------------------------------------------------
// Kernel 0a: round x -> g_xr (tf32, rna)
// ---------------------------------------------------------------------------
__global__ void round_x(const float* __restrict__ src, int n4) {
    int i = blockIdx.x * blockDim.x + threadIdx.x;
    if (i >= n4) return;
    float4 v = ((const float4*)src)[i];
    v.x = tf32r(v.x); v.y = tf32r(v.y); v.z = tf32r(v.z); v.w = tf32r(v.w);
    ((float4*)g_xr)[i] = v;
}

// ---------------------------------------------------------------------------
// Kernel 0b: transpose + round W[k][n] -> g_wt[n][k]
// ---------------------------------------------------------------------------
__global__ __launch_bounds__(256) void wtrans(const float* __restrict__ W) {
    __shared__ float t[32][33];
    const int x = threadIdx.x, y = threadIdx.y;   // 32 x 8
    const int n0 = blockIdx.x * 32, k0 = blockIdx.y * 32;
#pragma unroll
    for (int i = 0; i < 4; i++)
        t[y + i * 8][x] = W[(size_t)(k0 + y + i * 8) * D3 + n0 + x];
    __syncthreads();
#pragma unroll
    for (int i = 0; i < 4; i++) {
        int nn = y + i * 8;
        g_wt[(size_t)(n0 + nn) * DM + k0 + x] = tf32r(t[x][nn]);
    }
}

// ---------------------------------------------------------------------------
// Kernel 1: kqv = x @ w (tf32 mma.sync). CTA 128x128, BK=32,
// 4 warps with 64x64 warp tiles, double-buffered cp.async.
// Epilogue: tf32-round, Q chunk pre-scaled by log2(e)/32 (exp2-domain softmax).
// ---------------------------------------------------------------------------
static __device__ __forceinline__ void gemm_stage_load(float* As, float* Bs,
                                                       int bm, int bn, int k0, int tid) {
#pragma unroll
    for (int p = 0; p < 8; p++) {
        int idx = tid + p * 128;
        int r = idx >> 3, c8 = idx & 7;
        cpa16(s2u(As + r * LG + c8 * 4), g_xr + (size_t)(bm + r) * DM + k0 + c8 * 4);
        cpa16(s2u(Bs + r * LG + c8 * 4), g_wt + (size_t)(bn + r) * DM + k0 + c8 * 4);
    }
}

__global__ __launch_bounds__(128) void gemm_kqv() {
    extern __shared__ __align__(16) float gsm[];
    const int tid = threadIdx.x, lane = tid & 31, wid = tid >> 5;
    const int bm = blockIdx.y * 128, bn = blockIdx.x * 128;
    const int wm = (wid >> 1) * 64, wn = (wid & 1) * 64;

    float c[4][8][4];
#pragma unroll
    for (int i = 0; i < 4; i++)
#pragma unroll
        for (int j = 0; j < 8; j++)
#pragma unroll
            for (int e = 0; e < 4; e++) c[i][j][e] = 0.f;

    gemm_stage_load(gsm, gsm + 4608, bm, bn, 0, tid);
    CP_COMMIT();

    for (int kc = 0; kc < 32; kc++) {
        if (kc < 31) {
            float* base = gsm + ((kc + 1) & 1) * 9216;
            gemm_stage_load(base, base + 4608, bm, bn, (kc + 1) * 32, tid);
        }
        CP_COMMIT();
        CP_WAIT(1);
        __syncthreads();

        const float* As = gsm + (kc & 1) * 9216;
        const float* Bs = As + 4608;
#pragma unroll
        for (int ks = 0; ks < 4; ks++) {
            unsigned af[4][4], bf[4][4];
#pragma unroll
            for (int mt = 0; mt < 4; mt++) ldA(af[mt], As, wm + mt * 16, ks * 8, LG);
#pragma unroll
            for (int np = 0; np < 4; np++) ldB(bf[np], Bs, wn + np * 16, ks * 8, LG);
#pragma unroll
            for (int mt = 0; mt < 4; mt++)
#pragma unroll
                for (int np = 0; np < 4; np++) {
                    mma_tf32(c[mt][np * 2],     af[mt], bf[np]);
                    mma_tf32(c[mt][np * 2 + 1], af[mt], bf[np] + 2);
                }
        }
        __syncthreads();
    }

    // Q chunk pre-scale: log2(e)/sqrt(D) = 1.44269504/32
    const float scl = (bn >= DM && bn < 2 * DM) ? 0.04508422f : 1.0f;
#pragma unroll
    for (int mt = 0; mt < 4; mt++) {
        int r = bm + wm + mt * 16 + (lane >> 2);
#pragma unroll
        for (int nt = 0; nt < 8; nt++) {
            int col = bn + wn + nt * 8 + (lane & 3) * 2;
            *(float2*)&g_kqv[(size_t)r * D3 + col] =
                make_float2(tf32r(c[mt][nt][0] * scl), tf32r(c[mt][nt][1] * scl));
            *(float2*)&g_kqv[(size_t)(r + 8) * D3 + col] =
                make_float2(tf32r(c[mt][nt][2] * scl), tf32r(c[mt][nt][3] * scl));
        }
    }
}

// ---------------------------------------------------------------------------
// Kernel 1.5: transpose V chunk -> g_vT[c][j]
// ---------------------------------------------------------------------------
__global__ __launch_bounds__(256) void vtrans_kernel() {
    __shared__ float t[32][33];
    const int x = threadIdx.x, y = threadIdx.y;
    const int j0 = blockIdx.x * 32, c0 = blockIdx.y * 32;
#pragma unroll
    for (int k = 0; k < 4; k++)
        t[y + k * 8][x] = g_kqv[(size_t)(j0 + y + k * 8) * D3 + 2 * DM + c0 + x];
    __syncthreads();
#pragma unroll
    for (int k = 0; k < 4; k++)
        g_vT[(size_t)(c0 + y + k * 8) * SEQ + j0 + x] = t[x][y + k * 8];
}

// ---------------------------------------------------------------------------
// Kernel 2: flash attention — 4 warps x 32 rows, exp2-domain softmax,
// masked/unmasked softmax split. Pipeline identical to the 515us version.
// smem: QS[128][LA] | PS[128][LA] | KS[64][LA] | VT[64][LA] = 104448 B (2 CTAs/SM)
// ---------------------------------------------------------------------------
__global__ __launch_bounds__(128, 2) void attn_kernel(float* __restrict__ out) {
    extern __shared__ __align__(16) float sm[];
    float* QS = sm;
    float* PS = sm + 128 * LA;
    float* KS = sm + 256 * LA;
    float* VT = sm + 320 * LA;

    const int tid = threadIdx.x, lane = tid & 31, wid = tid >> 5;
    const int h = blockIdx.y;
    const int qt = (int)gridDim.x - 1 - (int)blockIdx.x;
    const int q0 = qt * 128;
    const int wr = wid * 32;
    // exp2 domain: slope' = slope * log2(e)
    const float slope = exp2f(-0.5f * (float)(h + 1)) * 1.44269504f;
    const int nt = 2 * qt + 2;

#pragma unroll
    for (int p = 0; p < 16; p++) {
        int ch = tid + p * 128;
        int r = ch >> 4, c4 = (ch & 15) * 4;
        cpa16(s2u(&QS[r * LA + c4]), g_kqv + (size_t)(q0 + r) * D3 + DM + h * 64 + c4);
    }
#pragma unroll
    for (int p = 0; p < 8; p++) {
        int ch = tid + p * 128;
        int r = ch >> 4, c4 = (ch & 15) * 4;
        cpa16(s2u(&KS[r * LA + c4]), g_kqv + (size_t)r * D3 + h * 64 + c4);
    }
    CP_COMMIT();

    float o0[8][4], o1[8][4];
#pragma unroll
    for (int ntl = 0; ntl < 8; ntl++)
#pragma unroll
        for (int e = 0; e < 4; e++) { o0[ntl][e] = 0.f; o1[ntl][e] = 0.f; }
    float m[4] = {-1e30f, -1e30f, -1e30f, -1e30f};
    float l[4] = {0.f, 0.f, 0.f, 0.f};

    // softmax for one 16-row m-tile; Domask selected statically by the caller
    auto softmax_mt = [&](float (*s)[4], float (*o)[4], int mt, int kv0, bool domask)
        __attribute__((always_inline)) {
        const int gi0 = q0 + wr + mt * 16 + (lane >> 2);
        float ml0 = -1e30f, ml1 = -1e30f;
#pragma unroll
        for (int ntl = 0; ntl < 8; ntl++) {
#pragma unroll
            for (int e = 0; e < 2; e++) {
                int gj = kv0 + ntl * 8 + (lane & 3) * 2 + e;
                float v0 = fmaf(slope, (float)(gj - gi0), s[ntl][e]);
                if (domask && gj > gi0) v0 = -1e30f;
                s[ntl][e] = v0; ml0 = fmaxf(ml0, v0);
                float v1 = fmaf(slope, (float)(gj - (gi0 + 8)), s[ntl][2 + e]);
                if (domask && gj > gi0 + 8) v1 = -1e30f;
                s[ntl][2 + e] = v1; ml1 = fmaxf(ml1, v1);
            }
        }
        ml0 = fmaxf(ml0, __shfl_xor_sync(0xffffffffu, ml0, 1));
        ml0 = fmaxf(ml0, __shfl_xor_sync(0xffffffffu, ml0, 2));
        ml1 = fmaxf(ml1, __shfl_xor_sync(0xffffffffu, ml1, 1));
        ml1 = fmaxf(ml1, __shfl_xor_sync(0xffffffffu, ml1, 2));
        float mn0 = fmaxf(m[2 * mt], ml0), mn1 = fmaxf(m[2 * mt + 1], ml1);
        float a0 = exp2f(m[2 * mt] - mn0), a1 = exp2f(m[2 * mt + 1] - mn1);
        m[2 * mt] = mn0; m[2 * mt + 1] = mn1;
        float rs0 = 0.f, rs1 = 0.f;
#pragma unroll
        for (int ntl = 0; ntl < 8; ntl++) {
#pragma unroll
            for (int e = 0; e < 2; e++) {
                float p0 = exp2f(s[ntl][e] - mn0);     s[ntl][e] = p0;     rs0 += p0;
                float p1 = exp2f(s[ntl][2 + e] - mn1); s[ntl][2 + e] = p1; rs1 += p1;
            }
        }
        rs0 += __shfl_xor_sync(0xffffffffu, rs0, 1);
        rs0 += __shfl_xor_sync(0xffffffffu, rs0, 2);
        rs1 += __shfl_xor_sync(0xffffffffu, rs1, 1);
        rs1 += __shfl_xor_sync(0xffffffffu, rs1, 2);
        l[2 * mt]     = l[2 * mt] * a0 + rs0;
        l[2 * mt + 1] = l[2 * mt + 1] * a1 + rs1;
#pragma unroll
        for (int ntl = 0; ntl < 8; ntl++) {
            o[ntl][0] *= a0; o[ntl][1] *= a0; o[ntl][2] *= a1; o[ntl][3] *= a1;
        }
        const int pr = wr + mt * 16 + (lane >> 2);
        const int pc = (lane & 3) * 2;
#pragma unroll
        for (int ntl = 0; ntl < 8; ntl++) {
            *(float2*)&PS[pr * LA + ntl * 8 + pc] =
                make_float2(tf32r(s[ntl][0]), tf32r(s[ntl][1]));
            *(float2*)&PS[(pr + 8) * LA + ntl * 8 + pc] =
                make_float2(tf32r(s[ntl][2]), tf32r(s[ntl][3]));
        }
    };

    for (int t = 0; t < nt; t++) {
        const int kv0 = t * 64;
        const bool active = (kv0 <= q0 + wr + 31);

#pragma unroll
        for (int p = 0; p < 8; p++) {
            int ch = tid + p * 128;
            int d = ch >> 4, j4 = (ch & 15) * 4;
            cpa16(s2u(&VT[d * LA + j4]), g_vT + (size_t)(h * 64 + d) * SEQ + kv0 + j4);
        }
        CP_COMMIT();

        CP_WAIT(1);
        __syncthreads();

        float s0[8][4], s1[8][4];
        if (active) {
#pragma unroll
            for (int ntl = 0; ntl < 8; ntl++)
#pragma unroll
                for (int e = 0; e < 4; e++) { s0[ntl][e] = 0.f; s1[ntl][e] = 0.f; }
#pragma unroll
            for (int ks = 0; ks < 8; ks++) {
                unsigned qf0[4], qf1[4];
                ldA(qf0, QS, wr,      ks * 8, LA);
                ldA(qf1, QS, wr + 16, ks * 8, LA);
#pragma unroll
                for (int np = 0; np < 4; np++) {
                    unsigned bf[4];
                    ldB(bf, KS, np * 16, ks * 8, LA);
                    mma_tf32(s0[np * 2],     qf0, bf);
                    mma_tf32(s0[np * 2 + 1], qf0, bf + 2);
                    mma_tf32(s1[np * 2],     qf1, bf);
                    mma_tf32(s1[np * 2 + 1], qf1, bf + 2);
                }
            }
        }
        __syncthreads();

        {
            const int kvn = (t + 1 < nt ? t + 1 : t) * 64;
#pragma unroll
            for (int p = 0; p < 8; p++) {
                int ch = tid + p * 128;
                int r = ch >> 4, c4 = (ch & 15) * 4;
                cpa16(s2u(&KS[r * LA + c4]), g_kqv + (size_t)(kvn + r) * D3 + h * 64 + c4);
            }
            CP_COMMIT();
        }

        if (active) {
            if (t >= nt - 2) {           // only diagonal-adjacent tiles mask
                softmax_mt(s0, o0, 0, kv0, true);
                softmax_mt(s1, o1, 1, kv0, true);
            } else {
                softmax_mt(s0, o0, 0, kv0, false);
                softmax_mt(s1, o1, 1, kv0, false);
            }
            __syncwarp();
        }

        CP_WAIT(1);
        __syncthreads();

        if (active) {
#pragma unroll
            for (int jk = 0; jk < 8; jk++) {
                unsigned pf0[4], pf1[4];
                ldA(pf0, PS, wr,      jk * 8, LA);
                ldA(pf1, PS, wr + 16, jk * 8, LA);
#pragma unroll
                for (int dp = 0; dp < 4; dp++) {
                    unsigned vf[4];
                    ldB(vf, VT, dp * 16, jk * 8, LA);
                    mma_tf32(o0[dp * 2],     pf0, vf);
                    mma_tf32(o0[dp * 2 + 1], pf0, vf + 2);
                    mma_tf32(o1[dp * 2],     pf1, vf);
                    mma_tf32(o1[dp * 2 + 1], pf1, vf + 2);
                }
            }
        }
        __syncthreads();
    }

    float rl[4] = {1.f / l[0], 1.f / l[1], 1.f / l[2], 1.f / l[3]};
#pragma unroll
    for (int mt = 0; mt < 2; mt++) {
        float (*o)[4] = mt ? o1 : o0;
        const int r = q0 + wr + mt * 16 + (lane >> 2);
#pragma unroll
        for (int ntl = 0; ntl < 8; ntl++) {
            int col = h * 64 + ntl * 8 + (lane & 3) * 2;
            *(float2*)&out[(size_t)r * DM + col] =
                make_float2(o[ntl][0] * rl[2 * mt], o[ntl][1] * rl[2 * mt]);
            *(float2*)&out[(size_t)(r + 8) * DM + col] =
                make_float2(o[ntl][2] * rl[2 * mt + 1], o[ntl][3] * rl[2 * mt + 1]);
        }
    }
}

// ---------------------------------------------------------------------------
// Launch
// ---------------------------------------------------------------------------
extern "C" void kernel_launch(void* const* d_in, const int* in_sizes, int n_in,
                              void* d_out, int out_size) {
    const float* x = (const float*)d_in[0];   // [1, 4096, 1024]
    const float* w = (const float*)d_in[1];   // [1024, 3072]
    float* out = (float*)d_out;

    const int gemm_smem = 2 * 2 * 128 * LG * (int)sizeof(float);   // 73728 B
    cudaFuncSetAttribute(gemm_kqv, cudaFuncAttributeMaxDynamicSharedMemorySize, gemm_smem);
    const int attn_smem = 384 * LA * (int)sizeof(float);           // 104448 B
    cudaFuncSetAttribute(attn_kernel, cudaFuncAttributeMaxDynamicSharedMemorySize, attn_smem);

    const int nx4 = SEQ * DM / 4;
    round_x<<<(nx4 + 255) / 256, 256>>>(x, nx4);
    wtrans<<<dim3(D3 / 32, DM / 32), dim3(32, 8)>>>(w);
    gemm_kqv<<<dim3(D3 / 128, SEQ / 128), 128, gemm_smem>>>();
    vtrans_kernel<<<dim3(SEQ / 32, DM / 32), dim3(32, 8)>>>();
    attn_kernel<<<dim3(SEQ / 128, NH), 128, attn_smem>>>(out);
}

// round 15
// speedup vs baseline: 1.7811x; 1.0324x over previous
#include <cuda_runtime.h>

#define SEQ 4096
#define DM  1024
#define NH  16
#define D3  3072
#define LA  68     // attn smem row stride (floats)
#define LG  36     // gemm smem row stride (floats)

// tf32-rounded operands for the projection GEMM
__device__ float g_xr[SEQ * DM];    // x, rounded
__device__ float g_wt[D3 * DM];     // W^T [n][k], rounded
// fp32 scratch: kqv K|Q chunks (V chunk unused), tf32-rounded, Q pre-scaled by log2e/32
__device__ float g_kqv[SEQ * D3];
// V transposed per feature: g_vT[h*64+d][j]  (written directly by gemm epilogue)
__device__ float g_vT[DM * SEQ];

// ---------------------------------------------------------------------------
// helpers
// ---------------------------------------------------------------------------
static __device__ __forceinline__ unsigned s2u(const void* p) {
    return (unsigned)__cvta_generic_to_shared(p);
}
static __device__ __forceinline__ void ldsm4(unsigned* r, unsigned a) {
    asm volatile("ldmatrix.sync.aligned.m8n8.x4.shared.b16 {%0,%1,%2,%3}, [%4];"
                 : "=r"(r[0]), "=r"(r[1]), "=r"(r[2]), "=r"(r[3]) : "r"(a));
}
static __device__ __forceinline__ float tf32r(float x) {
    unsigned u; asm("cvt.rna.tf32.f32 %0, %1;" : "=r"(u) : "f"(x));
    return __uint_as_float(u);
}
static __device__ __forceinline__ void mma_tf32(float* c, const unsigned* a, const unsigned* b) {
    asm volatile("mma.sync.aligned.m16n8k8.row.col.f32.tf32.tf32.f32 "
                 "{%0,%1,%2,%3}, {%4,%5,%6,%7}, {%8,%9}, {%0,%1,%2,%3};"
                 : "+f"(c[0]), "+f"(c[1]), "+f"(c[2]), "+f"(c[3])
                 : "r"(a[0]), "r"(a[1]), "r"(a[2]), "r"(a[3]), "r"(b[0]), "r"(b[1]));
}
static __device__ __forceinline__ void ldA(unsigned* a, const float* base, int r0, int c0, int ld) {
    const int lane = threadIdx.x & 31;
    int row = r0 + (lane & 7) + ((lane >> 3) & 1) * 8;
    int col = c0 + (lane >> 4) * 4;
    ldsm4(a, s2u(base + row * ld + col));
}
static __device__ __forceinline__ void ldB(unsigned* b, const float* base, int n0, int c0, int ld) {
    const int lane = threadIdx.x & 31;
    int row = n0 + (lane & 7) + (lane >> 4) * 8;
    int col = c0 + ((lane >> 3) & 1) * 4;
    ldsm4(b, s2u(base + row * ld + col));
}
static __device__ __forceinline__ void cpa16(unsigned s, const void* g) {
    asm volatile("cp.async.cg.shared.global [%0], [%1], 16;" :: "r"(s), "l"(g) : "memory");
}
#define CP_COMMIT() asm volatile("cp.async.commit_group;" ::: "memory")
#define CP_WAIT(n)  asm volatile("cp.async.wait_group %0;" :: "n"(n) : "memory")

// ---------------------------------------------------------------------------
// Kernel 0: merged prep — blocks [0,4096): round x; [4096,7168): transpose+round W
// ---------------------------------------------------------------------------
__global__ __launch_bounds__(256) void prep(const float* __restrict__ x,
                                            const float* __restrict__ W) {
    if (blockIdx.x < 4096) {
        int i = blockIdx.x * 256 + threadIdx.x;        // SEQ*DM/4 = 1048576 float4s
        float4 v = ((const float4*)x)[i];
        v.x = tf32r(v.x); v.y = tf32r(v.y); v.z = tf32r(v.z); v.w = tf32r(v.w);
        ((float4*)g_xr)[i] = v;
    } else {
        __shared__ float t[32][33];
        const int bid = blockIdx.x - 4096;             // 3072 blocks = 96 x 32
        const int n0 = (bid % 96) * 32, k0 = (bid / 96) * 32;
        const int xc = threadIdx.x & 31, y = threadIdx.x >> 5;   // 32 x 8
#pragma unroll
        for (int i = 0; i < 4; i++)
            t[y + i * 8][xc] = W[(size_t)(k0 + y + i * 8) * D3 + n0 + xc];
        __syncthreads();
#pragma unroll
        for (int i = 0; i < 4; i++) {
            int nn = y + i * 8;
            g_wt[(size_t)(n0 + nn) * DM + k0 + xc] = tf32r(t[xc][nn]);
        }
    }
}

// ---------------------------------------------------------------------------
// Kernel 1: kqv = x @ w (tf32 mma.sync). CTA 128x128, BK=32, 4 warps (64x64 tiles),
// double-buffered cp.async, ONE __syncthreads per K-chunk.
// Epilogue: K chunk -> g_kqv; Q chunk -> g_kqv scaled by log2e/32;
//           V chunk -> g_vT TRANSPOSED via smem staging (g_kqv V never written).
// ---------------------------------------------------------------------------
static __device__ __forceinline__ void gemm_stage_load(float* As, float* Bs,
                                                       int bm, int bn, int k0, int tid) {
#pragma unroll
    for (int p = 0; p < 8; p++) {
        int idx = tid + p * 128;
        int r = idx >> 3, c8 = idx & 7;
        cpa16(s2u(As + r * LG + c8 * 4), g_xr + (size_t)(bm + r) * DM + k0 + c8 * 4);
        cpa16(s2u(Bs + r * LG + c8 * 4), g_wt + (size_t)(bn + r) * DM + k0 + c8 * 4);
    }
}

__global__ __launch_bounds__(128) void gemm_kqv() {
    extern __shared__ __align__(16) float gsm[];
    const int tid = threadIdx.x, lane = tid & 31, wid = tid >> 5;
    const int bm = blockIdx.y * 128, bn = blockIdx.x * 128;
    const int wm = (wid >> 1) * 64, wn = (wid & 1) * 64;

    float c[4][8][4];
#pragma unroll
    for (int i = 0; i < 4; i++)
#pragma unroll
        for (int j = 0; j < 8; j++)
#pragma unroll
            for (int e = 0; e < 4; e++) c[i][j][e] = 0.f;

    gemm_stage_load(gsm, gsm + 4608, bm, bn, 0, tid);
    CP_COMMIT();

    for (int kc = 0; kc < 32; kc++) {
        CP_WAIT(0);          // chunk kc resident
        __syncthreads();     // visible to all; also proves compute(kc-1) done => other buf free
        if (kc < 31) {
            float* base = gsm + ((kc + 1) & 1) * 9216;
            gemm_stage_load(base, base + 4608, bm, bn, (kc + 1) * 32, tid);
            CP_COMMIT();
        }
        const float* As = gsm + (kc & 1) * 9216;
        const float* Bs = As + 4608;
#pragma unroll
        for (int ks = 0; ks < 4; ks++) {
            unsigned af[4][4], bf[4][4];
#pragma unroll
            for (int mt = 0; mt < 4; mt++) ldA(af[mt], As, wm + mt * 16, ks * 8, LG);
#pragma unroll
            for (int np = 0; np < 4; np++) ldB(bf[np], Bs, wn + np * 16, ks * 8, LG);
#pragma unroll
            for (int mt = 0; mt < 4; mt++)
#pragma unroll
                for (int np = 0; np < 4; np++) {
                    mma_tf32(c[mt][np * 2],     af[mt], bf[np]);
                    mma_tf32(c[mt][np * 2 + 1], af[mt], bf[np] + 2);
                }
        }
    }

    if (bn < 2 * DM) {
        // K / Q chunks -> g_kqv.  Q pre-scale: log2(e)/sqrt(D) = 1.44269504/32
        const float scl = (bn >= DM) ? 0.04508422f : 1.0f;
#pragma unroll
        for (int mt = 0; mt < 4; mt++) {
            int r = bm + wm + mt * 16 + (lane >> 2);
#pragma unroll
            for (int nt = 0; nt < 8; nt++) {
                int col = bn + wn + nt * 8 + (lane & 3) * 2;
                *(float2*)&g_kqv[(size_t)r * D3 + col] =
                    make_float2(tf32r(c[mt][nt][0] * scl), tf32r(c[mt][nt][1] * scl));
                *(float2*)&g_kqv[(size_t)(r + 8) * D3 + col] =
                    make_float2(tf32r(c[mt][nt][2] * scl), tf32r(c[mt][nt][3] * scl));
            }
        }
    } else {
        // V chunk -> g_vT transposed. Stage T[col][row] in smem (stride 132,
        // store bank = 8j+q -> conflict-free), then coalesced float4 writes.
        __syncthreads();     // mainloop smem reads complete in all warps
        float* T = gsm;      // 128 x 132 floats = 67584 B <= 73728 B
#pragma unroll
        for (int mt = 0; mt < 4; mt++) {
            int rr = wm + mt * 16 + (lane >> 2);
#pragma unroll
            for (int nt = 0; nt < 8; nt++) {
                int cc = wn + nt * 8 + (lane & 3) * 2;
                T[cc * 132 + rr]           = c[mt][nt][0];
                T[(cc + 1) * 132 + rr]     = c[mt][nt][1];
                T[cc * 132 + rr + 8]       = c[mt][nt][2];
                T[(cc + 1) * 132 + rr + 8] = c[mt][nt][3];
            }
        }
        __syncthreads();
#pragma unroll
        for (int p = 0; p < 32; p++) {
            int i = tid + p * 128;
            int cc = i >> 5, r4 = (i & 31) * 4;
            float4 v = *(float4*)&T[cc * 132 + r4];
            v.x = tf32r(v.x); v.y = tf32r(v.y); v.z = tf32r(v.z); v.w = tf32r(v.w);
            *(float4*)&g_vT[(size_t)(bn - 2 * DM + cc) * SEQ + bm + r4] = v;
        }
    }
}

// ---------------------------------------------------------------------------
// Kernel 2: flash attention — UNCHANGED from the 509us version.
// 4 warps x 32 rows, exp2-domain softmax, masked/unmasked split.
// smem: QS[128][LA] | PS[128][LA] | KS[64][LA] | VT[64][LA] = 104448 B (2 CTAs/SM)
// ---------------------------------------------------------------------------
__global__ __launch_bounds__(128, 2) void attn_kernel(float* __restrict__ out) {
    extern __shared__ __align__(16) float sm[];
    float* QS = sm;
    float* PS = sm + 128 * LA;
    float* KS = sm + 256 * LA;
    float* VT = sm + 320 * LA;

    const int tid = threadIdx.x, lane = tid & 31, wid = tid >> 5;
    const int h = blockIdx.y;
    const int qt = (int)gridDim.x - 1 - (int)blockIdx.x;
    const int q0 = qt * 128;
    const int wr = wid * 32;
    const float slope = exp2f(-0.5f * (float)(h + 1)) * 1.44269504f;
    const int nt = 2 * qt + 2;

#pragma unroll
    for (int p = 0; p < 16; p++) {
        int ch = tid + p * 128;
        int r = ch >> 4, c4 = (ch & 15) * 4;
        cpa16(s2u(&QS[r * LA + c4]), g_kqv + (size_t)(q0 + r) * D3 + DM + h * 64 + c4);
    }
#pragma unroll
    for (int p = 0; p < 8; p++) {
        int ch = tid + p * 128;
        int r = ch >> 4, c4 = (ch & 15) * 4;
        cpa16(s2u(&KS[r * LA + c4]), g_kqv + (size_t)r * D3 + h * 64 + c4);
    }
    CP_COMMIT();

    float o0[8][4], o1[8][4];
#pragma unroll
    for (int ntl = 0; ntl < 8; ntl++)
#pragma unroll
        for (int e = 0; e < 4; e++) { o0[ntl][e] = 0.f; o1[ntl][e] = 0.f; }
    float m[4] = {-1e30f, -1e30f, -1e30f, -1e30f};
    float l[4] = {0.f, 0.f, 0.f, 0.f};

    auto softmax_mt = [&](float (*s)[4], float (*o)[4], int mt, int kv0, bool domask)
        __attribute__((always_inline)) {
        const int gi0 = q0 + wr + mt * 16 + (lane >> 2);
        float ml0 = -1e30f, ml1 = -1e30f;
#pragma unroll
        for (int ntl = 0; ntl < 8; ntl++) {
#pragma unroll
            for (int e = 0; e < 2; e++) {
                int gj = kv0 + ntl * 8 + (lane & 3) * 2 + e;
                float v0 = fmaf(slope, (float)(gj - gi0), s[ntl][e]);
                if (domask && gj > gi0) v0 = -1e30f;
                s[ntl][e] = v0; ml0 = fmaxf(ml0, v0);
                float v1 = fmaf(slope, (float)(gj - (gi0 + 8)), s[ntl][2 + e]);
                if (domask && gj > gi0 + 8) v1 = -1e30f;
                s[ntl][2 + e] = v1; ml1 = fmaxf(ml1, v1);
            }
        }
        ml0 = fmaxf(ml0, __shfl_xor_sync(0xffffffffu, ml0, 1));
        ml0 = fmaxf(ml0, __shfl_xor_sync(0xffffffffu, ml0, 2));
        ml1 = fmaxf(ml1, __shfl_xor_sync(0xffffffffu, ml1, 1));
        ml1 = fmaxf(ml1, __shfl_xor_sync(0xffffffffu, ml1, 2));
        float mn0 = fmaxf(m[2 * mt], ml0), mn1 = fmaxf(m[2 * mt + 1], ml1);
        float a0 = exp2f(m[2 * mt] - mn0), a1 = exp2f(m[2 * mt + 1] - mn1);
        m[2 * mt] = mn0; m[2 * mt + 1] = mn1;
        float rs0 = 0.f, rs1 = 0.f;
#pragma unroll
        for (int ntl = 0; ntl < 8; ntl++) {
#pragma unroll
            for (int e = 0; e < 2; e++) {
                float p0 = exp2f(s[ntl][e] - mn0);     s[ntl][e] = p0;     rs0 += p0;
                float p1 = exp2f(s[ntl][2 + e] - mn1); s[ntl][2 + e] = p1; rs1 += p1;
            }
        }
        rs0 += __shfl_xor_sync(0xffffffffu, rs0, 1);
        rs0 += __shfl_xor_sync(0xffffffffu, rs0, 2);
        rs1 += __shfl_xor_sync(0xffffffffu, rs1, 1);
        rs1 += __shfl_xor_sync(0xffffffffu, rs1, 2);
        l[2 * mt]     = l[2 * mt] * a0 + rs0;
        l[2 * mt + 1] = l[2 * mt + 1] * a1 + rs1;
#pragma unroll
        for (int ntl = 0; ntl < 8; ntl++) {
            o[ntl][0] *= a0; o[ntl][1] *= a0; o[ntl][2] *= a1; o[ntl][3] *= a1;
        }
        const int pr = wr + mt * 16 + (lane >> 2);
        const int pc = (lane & 3) * 2;
#pragma unroll
        for (int ntl = 0; ntl < 8; ntl++) {
            *(float2*)&PS[pr * LA + ntl * 8 + pc] =
                make_float2(tf32r(s[ntl][0]), tf32r(s[ntl][1]));
            *(float2*)&PS[(pr + 8) * LA + ntl * 8 + pc] =
                make_float2(tf32r(s[ntl][2]), tf32r(s[ntl][3]));
        }
    };

    for (int t = 0; t < nt; t++) {
        const int kv0 = t * 64;
        const bool active = (kv0 <= q0 + wr + 31);

#pragma unroll
        for (int p = 0; p < 8; p++) {
            int ch = tid + p * 128;
            int d = ch >> 4, j4 = (ch & 15) * 4;
            cpa16(s2u(&VT[d * LA + j4]), g_vT + (size_t)(h * 64 + d) * SEQ + kv0 + j4);
        }
        CP_COMMIT();

        CP_WAIT(1);
        __syncthreads();

        float s0[8][4], s1[8][4];
        if (active) {
#pragma unroll
            for (int ntl = 0; ntl < 8; ntl++)
#pragma unroll
                for (int e = 0; e < 4; e++) { s0[ntl][e] = 0.f; s1[ntl][e] = 0.f; }
#pragma unroll
            for (int ks = 0; ks < 8; ks++) {
                unsigned qf0[4], qf1[4];
                ldA(qf0, QS, wr,      ks * 8, LA);
                ldA(qf1, QS, wr + 16, ks * 8, LA);
#pragma unroll
                for (int np = 0; np < 4; np++) {
                    unsigned bf[4];
                    ldB(bf, KS, np * 16, ks * 8, LA);
                    mma_tf32(s0[np * 2],     qf0, bf);
                    mma_tf32(s0[np * 2 + 1], qf0, bf + 2);
                    mma_tf32(s1[np * 2],     qf1, bf);
                    mma_tf32(s1[np * 2 + 1], qf1, bf + 2);
                }
            }
        }
        __syncthreads();

        {
            const int kvn = (t + 1 < nt ? t + 1 : t) * 64;
#pragma unroll
            for (int p = 0; p < 8; p++) {
                int ch = tid + p * 128;
                int r = ch >> 4, c4 = (ch & 15) * 4;
                cpa16(s2u(&KS[r * LA + c4]), g_kqv + (size_t)(kvn + r) * D3 + h * 64 + c4);
            }
            CP_COMMIT();
        }

        if (active) {
            if (t >= nt - 2) {
                softmax_mt(s0, o0, 0, kv0, true);
                softmax_mt(s1, o1, 1, kv0, true);
            } else {
                softmax_mt(s0, o0, 0, kv0, false);
                softmax_mt(s1, o1, 1, kv0, false);
            }
            __syncwarp();
        }

        CP_WAIT(1);
        __syncthreads();

        if (active) {
#pragma unroll
            for (int jk = 0; jk < 8; jk++) {
                unsigned pf0[4], pf1[4];
                ldA(pf0, PS, wr,      jk * 8, LA);
                ldA(pf1, PS, wr + 16, jk * 8, LA);
#pragma unroll
                for (int dp = 0; dp < 4; dp++) {
                    unsigned vf[4];
                    ldB(vf, VT, dp * 16, jk * 8, LA);
                    mma_tf32(o0[dp * 2],     pf0, vf);
                    mma_tf32(o0[dp * 2 + 1], pf0, vf + 2);
                    mma_tf32(o1[dp * 2],     pf1, vf);
                    mma_tf32(o1[dp * 2 + 1], pf1, vf + 2);
                }
            }
        }
        __syncthreads();
    }

    float rl[4] = {1.f / l[0], 1.f / l[1], 1.f / l[2], 1.f / l[3]};
#pragma unroll
    for (int mt = 0; mt < 2; mt++) {
        float (*o)[4] = mt ? o1 : o0;
        const int r = q0 + wr + mt * 16 + (lane >> 2);
#pragma unroll
        for (int ntl = 0; ntl < 8; ntl++) {
            int col = h * 64 + ntl * 8 + (lane & 3) * 2;
            *(float2*)&out[(size_t)r * DM + col] =
                make_float2(o[ntl][0] * rl[2 * mt], o[ntl][1] * rl[2 * mt]);
            *(float2*)&out[(size_t)(r + 8) * DM + col] =
                make_float2(o[ntl][2] * rl[2 * mt + 1], o[ntl][3] * rl[2 * mt + 1]);
        }
    }
}

// ---------------------------------------------------------------------------
// Launch
// ---------------------------------------------------------------------------
extern "C" void kernel_launch(void* const* d_in, const int* in_sizes, int n_in,
                              void* d_out, int out_size) {
    const float* x = (const float*)d_in[0];   // [1, 4096, 1024]
    const float* w = (const float*)d_in[1];   // [1024, 3072]
    float* out = (float*)d_out;

    const int gemm_smem = 2 * 2 * 128 * LG * (int)sizeof(float);   // 73728 B
    cudaFuncSetAttribute(gemm_kqv, cudaFuncAttributeMaxDynamicSharedMemorySize, gemm_smem);
    const int attn_smem = 384 * LA * (int)sizeof(float);           // 104448 B
    cudaFuncSetAttribute(attn_kernel, cudaFuncAttributeMaxDynamicSharedMemorySize, attn_smem);

    prep<<<4096 + 3072, 256>>>(x, w);                       // round x | transpose+round W
    gemm_kqv<<<dim3(D3 / 128, SEQ / 128), 128, gemm_smem>>>();
    attn_kernel<<<dim3(SEQ / 128, NH), 128, attn_smem>>>(out);
}